// round 4
// baseline (speedup 1.0000x reference)
#include <cuda_runtime.h>
#include <math.h>

// ---------------------------------------------------------------------------
// Problem constants (fixed by the dataset)
// ---------------------------------------------------------------------------
#define D_C      128
#define PITCH    132          // smem row pitch in floats (132%4==0 -> 16B aligned rows)
#define MAX_ITEMS 200000

// Scratch for the 3 item->item aggregation results (3 * 200000 * 128 floats).
// Static __device__ array: the sanctioned no-alloc scratch mechanism.
__device__ float g_nb[(size_t)3 * MAX_ITEMS * D_C];

// ---------------------------------------------------------------------------
// SpMM: out[dst[e]] += val[e] * x[src[e]]   (scatter-add, one warp per edge)
// Coalesced 128B gathers + coalesced 128B atomic reductions (RED in SASS).
// ---------------------------------------------------------------------------
__global__ void spmm_kernel(const int* __restrict__ src,
                            const int* __restrict__ dst,
                            const float* __restrict__ val,
                            const float* __restrict__ x,
                            float* __restrict__ out,
                            int nE)
{
    int e = blockIdx.x * (blockDim.x >> 5) + (threadIdx.x >> 5);
    if (e >= nE) return;
    int lane = threadIdx.x & 31;

    int   s = __ldg(src + e);
    int   d = __ldg(dst + e);
    float v = __ldg(val + e);

    const float* xr = x   + (size_t)s * D_C;
    float*       o  = out + (size_t)d * D_C;

#pragma unroll
    for (int i = 0; i < 4; i++) {
        float a = __ldg(xr + lane + 32 * i) * v;
        atomicAdd(o + lane + 32 * i, a);   // result unused -> RED.E.ADD.F32
    }
}

// ---------------------------------------------------------------------------
// Score + combine kernel.
// Per block: 128 rows. For each relation:
//   phase A: stage I (128x128) and z = x (*) nb (128 rows x 128) into SMEM
//   phase B: H = Z @ I via 8-row x 4-col register tiles with fma.rn.f32x2
//            (f32x2 halves = even-k / odd-k partial sums), then
//            s = inv_sqrt_d * sum_j leaky_relu(h_j) via warp shuffles.
// Epilogue: softmax over the 3 scores, neighbor = sum_r w_r * nb_r.
// ---------------------------------------------------------------------------
__device__ __forceinline__ unsigned long long ld_u64_smem(const float* p)
{
    return *reinterpret_cast<const unsigned long long*>(p);
}

__global__ void __launch_bounds__(512, 1)
score_kernel(const float* __restrict__ x,
             const float* __restrict__ nb0,
             const float* __restrict__ nb1,
             const float* __restrict__ nb2,
             const float* __restrict__ I0,
             const float* __restrict__ I1,
             const float* __restrict__ I2,
             float* __restrict__ out,
             int nrows)
{
    extern __shared__ float sm[];
    float* I_sh = sm;                      // 128 * PITCH floats
    float* z_sh = sm + D_C * PITCH;        // 128 * PITCH floats
    float* s_sh = sm + 2 * D_C * PITCH;    // 3 * 128 floats

    const int tid  = threadIdx.x;
    const int lane = tid & 31;
    const int wid  = tid >> 5;             // 16 warps
    const int r0   = wid << 3;             // 8 rows per warp
    const int row0 = blockIdx.x * 128;
    const int rows = min(128, nrows - row0);

    const float4* xg = reinterpret_cast<const float4*>(x);

#pragma unroll 1
    for (int rel = 0; rel < 3; rel++) {
        const float* nbp = (rel == 0) ? nb0 : (rel == 1) ? nb1 : nb2;
        const float* Ip  = (rel == 0) ? I0  : (rel == 1) ? I1  : I2;

        // ---- phase A: stage I[k][j] (k-major, padded pitch) -----------------
        const float4* Ig = reinterpret_cast<const float4*>(Ip);
        for (int idx = tid; idx < D_C * 32; idx += 512) {
            int k  = idx >> 5;
            int j4 = idx & 31;
            float4 v = Ig[(k << 5) + j4];
            *reinterpret_cast<float4*>(&I_sh[k * PITCH + (j4 << 2)]) = v;
        }
        // ---- stage z = x * nb (row-major, padded pitch) ---------------------
        const float4* ng = reinterpret_cast<const float4*>(nbp);
        for (int idx = tid; idx < 128 * 32; idx += 512) {
            int r  = idx >> 5;
            int k4 = idx & 31;
            float4 zv = make_float4(0.f, 0.f, 0.f, 0.f);
            if (r < rows) {
                size_t off = (size_t)(row0 + r) * 32 + k4;
                float4 a = xg[off];
                float4 b = ng[off];
                zv.x = a.x * b.x; zv.y = a.y * b.y;
                zv.z = a.z * b.z; zv.w = a.w * b.w;
            }
            *reinterpret_cast<float4*>(&z_sh[r * PITCH + (k4 << 2)]) = zv;
        }
        __syncthreads();

        // ---- phase B: 8 rows x 4 interleaved cols (j = lane + 32c) ----------
        unsigned long long acc[8][4];
#pragma unroll
        for (int r = 0; r < 8; r++)
#pragma unroll
            for (int c = 0; c < 4; c++) acc[r][c] = 0ull;

        for (int k = 0; k < 128; k += 2) {
            unsigned long long zp[8];
#pragma unroll
            for (int r = 0; r < 8; r++)
                zp[r] = ld_u64_smem(&z_sh[(r0 + r) * PITCH + k]);  // {z[k], z[k+1]}
#pragma unroll
            for (int c = 0; c < 4; c++) {
                float ia = I_sh[k * PITCH + lane + 32 * c];
                float ib = I_sh[(k + 1) * PITCH + lane + 32 * c];
                unsigned long long bp;
                asm("mov.b64 %0, {%1, %2};" : "=l"(bp) : "f"(ia), "f"(ib));
#pragma unroll
                for (int r = 0; r < 8; r++)
                    asm("fma.rn.f32x2 %0, %1, %2, %0;"
                        : "+l"(acc[r][c]) : "l"(zp[r]), "l"(bp));
            }
        }

        // ---- leaky_relu + column sum + warp reduce --------------------------
#pragma unroll
        for (int r = 0; r < 8; r++) {
            float rs = 0.f;
#pragma unroll
            for (int c = 0; c < 4; c++) {
                float lo = __int_as_float((int)(acc[r][c] & 0xffffffffull));
                float hi = __int_as_float((int)(acc[r][c] >> 32));
                float h  = lo + hi;                     // full dot product h_j
                rs += (h >= 0.f) ? h : 0.2f * h;        // leaky_relu
            }
#pragma unroll
            for (int off = 16; off > 0; off >>= 1)
                rs += __shfl_xor_sync(0xffffffffu, rs, off);
            if (lane == 0)
                s_sh[rel * 128 + r0 + r] = rs * 0.08838834764831845f; // 1/sqrt(128)
        }
        __syncthreads();   // protect I_sh/z_sh reuse and publish s_sh
    }

    // ---- phase C: softmax over relations + weighted combine -----------------
    const float4* n0g = reinterpret_cast<const float4*>(nb0);
    const float4* n1g = reinterpret_cast<const float4*>(nb1);
    const float4* n2g = reinterpret_cast<const float4*>(nb2);
    float4* og = reinterpret_cast<float4*>(out);

    for (int idx = tid; idx < 128 * 32; idx += 512) {
        int r  = idx >> 5;
        int c4 = idx & 31;
        if (r >= rows) continue;
        float s0 = s_sh[r];
        float s1 = s_sh[128 + r];
        float s2 = s_sh[256 + r];
        float m  = fmaxf(s0, fmaxf(s1, s2));
        float e0 = __expf(s0 - m);
        float e1 = __expf(s1 - m);
        float e2 = __expf(s2 - m);
        float inv = 1.f / (e0 + e1 + e2);
        float w0 = e0 * inv, w1 = e1 * inv, w2 = e2 * inv;

        size_t off = (size_t)(row0 + r) * 32 + c4;
        float4 a = n0g[off], b = n1g[off], c = n2g[off];
        float4 o;
        o.x = w0 * a.x + w1 * b.x + w2 * c.x;
        o.y = w0 * a.y + w1 * b.y + w2 * c.y;
        o.z = w0 * a.z + w1 * b.z + w2 * c.z;
        o.w = w0 * a.w + w1 * b.w + w2 * c.w;
        og[off] = o;
    }
}

// ---------------------------------------------------------------------------
// Launch
// ---------------------------------------------------------------------------
extern "C" void kernel_launch(void* const* d_in, const int* in_sizes, int n_in,
                              void* d_out, int out_size)
{
    // The scalar "b" may or may not occupy slot 0; detect by size.
    int base = (in_sizes[0] == 1) ? 1 : 0;

    const float* x      = (const float*)d_in[base + 0];
    const int*   src0   = (const int*  )d_in[base + 1];
    const int*   dst0   = (const int*  )d_in[base + 2];
    const float* val0   = (const float*)d_in[base + 3];
    const int*   src1   = (const int*  )d_in[base + 4];
    const int*   dst1   = (const int*  )d_in[base + 5];
    const float* val1   = (const float*)d_in[base + 6];
    const int*   src2   = (const int*  )d_in[base + 7];
    const int*   dst2   = (const int*  )d_in[base + 8];
    const float* val2   = (const float*)d_in[base + 9];
    const int*   src_ui = (const int*  )d_in[base + 10];
    const int*   dst_ui = (const int*  )d_in[base + 11];
    const float* val_ui = (const float*)d_in[base + 12];
    const float* I0     = (const float*)d_in[base + 13];
    const float* I1     = (const float*)d_in[base + 14];
    const float* I2     = (const float*)d_in[base + 15];

    int n_items = in_sizes[base + 0] / D_C;
    int E0  = in_sizes[base + 1];
    int E1  = in_sizes[base + 4];
    int E2  = in_sizes[base + 7];
    int Eui = in_sizes[base + 10];
    int n_users = out_size / D_C - n_items;

    float* out_f    = (float*)d_out;
    float* u_emb    = out_f;                                // tuple order: (u_emb, neighbor)
    float* neighbor = out_f + (size_t)n_users * D_C;

    float* nb_base = nullptr;
    cudaGetSymbolAddress((void**)&nb_base, g_nb);
    float* nb0 = nb_base;
    float* nb1 = nb_base + (size_t)n_items * D_C;
    float* nb2 = nb_base + (size_t)2 * n_items * D_C;

    // Zero the accumulation targets (d_out is poisoned; g_nb carries old data).
    cudaMemsetAsync(nb_base, 0, (size_t)3 * n_items * D_C * sizeof(float), 0);
    cudaMemsetAsync(u_emb,   0, (size_t)n_users * D_C * sizeof(float), 0);

    // SpMMs: 8 edges per 256-thread block (one warp per edge).
    dim3 blk(256);
    spmm_kernel<<<(E0  + 7) / 8, blk>>>(src0,   dst0,   val0,   x, nb0,   E0 );
    spmm_kernel<<<(E1  + 7) / 8, blk>>>(src1,   dst1,   val1,   x, nb1,   E1 );
    spmm_kernel<<<(E2  + 7) / 8, blk>>>(src2,   dst2,   val2,   x, nb2,   E2 );
    spmm_kernel<<<(Eui + 7) / 8, blk>>>(src_ui, dst_ui, val_ui, x, u_emb, Eui);

    // Score + combine.
    const int smem_bytes = (2 * D_C * PITCH + 3 * 128) * (int)sizeof(float); // 136704 B
    cudaFuncSetAttribute(score_kernel,
                         cudaFuncAttributeMaxDynamicSharedMemorySize, smem_bytes);
    int nblocks = (n_items + 127) / 128;
    score_kernel<<<nblocks, 512, smem_bytes>>>(x, nb0, nb1, nb2, I0, I1, I2,
                                               neighbor, n_items);
}

// round 6
// speedup vs baseline: 1.1471x; 1.1471x over previous
#include <cuda_runtime.h>
#include <math.h>

// ---------------------------------------------------------------------------
// Problem constants (fixed by the dataset)
// ---------------------------------------------------------------------------
#define D_C       128
#define PITCH     132          // z_sh row pitch (floats), 16B-aligned rows
#define PITCHI    264          // paired-I row pitch (floats), 8B-aligned lanes
#define MAX_ITEMS 200000

// Scratch for the 3 item->item aggregation results.
__device__ float g_nb[(size_t)3 * MAX_ITEMS * D_C];

// ---------------------------------------------------------------------------
// SpMM v3: out[dst[e]] += val[e] * x[src[e]]
//  - one warp processes 4 edges; each lane owns 16B (float4) of the 512B row
//  - gathers: ld.global.nc.L2::cache_hint.v4.f32 with an evict_last policy
//    (pin x in L2 — it is re-read ~56x per row across the 4 spmms)
//  - scatters: red.global.add.L2::cache_hint.v4.f32 with an evict_first
//    policy (the streaming accumulator lines evict each other, not x)
// ---------------------------------------------------------------------------
__global__ void __launch_bounds__(256)
spmm_kernel(const int* __restrict__ src,
            const int* __restrict__ dst,
            const float* __restrict__ val,
            const float* __restrict__ x,
            float* __restrict__ out,
            int nE)
{
    const int lane = threadIdx.x & 31;
    const int warp = (blockIdx.x * blockDim.x + threadIdx.x) >> 5;
    const int e0 = warp * 4;
    if (e0 >= nE) return;
    const int cnt = min(4, nE - e0);

    unsigned long long pol_last, pol_first;
    asm("createpolicy.fractional.L2::evict_last.b64 %0, 1.0;"  : "=l"(pol_last));
    asm("createpolicy.fractional.L2::evict_first.b64 %0, 1.0;" : "=l"(pol_first));

    float4 a[4];
    int dd[4];

#pragma unroll
    for (int j = 0; j < 4; j++) {
        if (j < cnt) {
            int   s = __ldg(src + e0 + j);
            dd[j]   = __ldg(dst + e0 + j);
            float v = __ldg(val + e0 + j);
            const float* p = x + (size_t)s * D_C + lane * 4;
            float4 t;
            asm volatile("ld.global.nc.L2::cache_hint.v4.f32 {%0,%1,%2,%3}, [%4], %5;"
                         : "=f"(t.x), "=f"(t.y), "=f"(t.z), "=f"(t.w)
                         : "l"(p), "l"(pol_last));
            a[j].x = t.x * v; a[j].y = t.y * v;
            a[j].z = t.z * v; a[j].w = t.w * v;
        }
    }
#pragma unroll
    for (int j = 0; j < 4; j++) {
        if (j < cnt) {
            float* q = out + (size_t)dd[j] * D_C + lane * 4;
            asm volatile("red.global.add.L2::cache_hint.v4.f32 [%0], {%1,%2,%3,%4}, %5;"
                         :: "l"(q), "f"(a[j].x), "f"(a[j].y),
                            "f"(a[j].z), "f"(a[j].w), "l"(pol_first)
                         : "memory");
        }
    }
}

// ---------------------------------------------------------------------------
// Score + combine kernel (128 rows / block, 512 threads).
// Phase A: stage I as interleaved k-pairs (one LDS.64 yields {I[k][j],I[k+1][j]})
//          and z = x (*) nb, both in padded SMEM.
// Phase B: H = Z @ I with fma.rn.f32x2 (FFMA2), 8-row x 4-col register tiles;
//          f32x2 halves are even-k / odd-k partial sums, summed before leaky.
// Phase C: softmax over the 3 relation scores, neighbor = sum_r w_r * nb_r.
// ---------------------------------------------------------------------------
__device__ __forceinline__ unsigned long long ld_u64_smem(const float* p)
{
    return *reinterpret_cast<const unsigned long long*>(p);
}

__global__ void __launch_bounds__(512, 1)
score_kernel(const float* __restrict__ x,
             const float* __restrict__ nb0,
             const float* __restrict__ nb1,
             const float* __restrict__ nb2,
             const float* __restrict__ I0,
             const float* __restrict__ I1,
             const float* __restrict__ I2,
             float* __restrict__ out,
             int nrows)
{
    extern __shared__ float sm[];
    float* I_sh = sm;                          // 64 * PITCHI floats (paired rows)
    float* z_sh = sm + 64 * PITCHI;            // 128 * PITCH floats
    float* s_sh = sm + 64 * PITCHI + D_C * PITCH;  // 3 * 128 floats

    const int tid  = threadIdx.x;
    const int lane = tid & 31;
    const int wid  = tid >> 5;                 // 16 warps
    const int r0   = wid << 3;                 // 8 rows per warp
    const int row0 = blockIdx.x * 128;
    const int rows = min(128, nrows - row0);

    const float4* xg = reinterpret_cast<const float4*>(x);

#pragma unroll 1
    for (int rel = 0; rel < 3; rel++) {
        const float* nbp = (rel == 0) ? nb0 : (rel == 1) ? nb1 : nb2;
        const float* Ip  = (rel == 0) ? I0  : (rel == 1) ? I1  : I2;

        // ---- stage I as k-pair-interleaved rows -----------------------------
        const float4* Ig = reinterpret_cast<const float4*>(Ip);
        for (int idx = tid; idx < 64 * 32; idx += 512) {
            int p  = idx >> 5;                 // k-pair index (k = 2p, 2p+1)
            int j4 = idx & 31;                 // group of 4 columns
            float4 ae = Ig[(2 * p)     * 32 + j4];
            float4 ao = Ig[(2 * p + 1) * 32 + j4];
            float* w = &I_sh[p * PITCHI + (j4 << 3)];
            float4 w0 = make_float4(ae.x, ao.x, ae.y, ao.y);
            float4 w1 = make_float4(ae.z, ao.z, ae.w, ao.w);
            *reinterpret_cast<float4*>(w)     = w0;
            *reinterpret_cast<float4*>(w + 4) = w1;
        }
        // ---- stage z = x * nb ----------------------------------------------
        const float4* ng = reinterpret_cast<const float4*>(nbp);
        for (int idx = tid; idx < 128 * 32; idx += 512) {
            int r  = idx >> 5;
            int k4 = idx & 31;
            float4 zv = make_float4(0.f, 0.f, 0.f, 0.f);
            if (r < rows) {
                size_t off = (size_t)(row0 + r) * 32 + k4;
                float4 av = xg[off];
                float4 bv = ng[off];
                zv.x = av.x * bv.x; zv.y = av.y * bv.y;
                zv.z = av.z * bv.z; zv.w = av.w * bv.w;
            }
            *reinterpret_cast<float4*>(&z_sh[r * PITCH + (k4 << 2)]) = zv;
        }
        __syncthreads();

        // ---- phase B: register-tiled matvec with FFMA2 ----------------------
        unsigned long long acc[8][4];
#pragma unroll
        for (int r = 0; r < 8; r++)
#pragma unroll
            for (int c = 0; c < 4; c++) acc[r][c] = 0ull;

        for (int p = 0; p < 64; p++) {
            unsigned long long zp[8];
#pragma unroll
            for (int r = 0; r < 8; r++)        // broadcast LDS.64: {z[2p], z[2p+1]}
                zp[r] = ld_u64_smem(&z_sh[(r0 + r) * PITCH + 2 * p]);
#pragma unroll
            for (int c = 0; c < 4; c++) {
                // {I[2p][j], I[2p+1][j]} in one LDS.64, j = lane + 32c
                unsigned long long bp =
                    ld_u64_smem(&I_sh[p * PITCHI + ((lane + 32 * c) << 1)]);
#pragma unroll
                for (int r = 0; r < 8; r++)
                    asm("fma.rn.f32x2 %0, %1, %2, %0;"
                        : "+l"(acc[r][c]) : "l"(zp[r]), "l"(bp));
            }
        }

        // ---- leaky_relu + column sum + warp reduce --------------------------
#pragma unroll
        for (int r = 0; r < 8; r++) {
            float rs = 0.f;
#pragma unroll
            for (int c = 0; c < 4; c++) {
                float lo = __int_as_float((int)(acc[r][c] & 0xffffffffull));
                float hi = __int_as_float((int)(acc[r][c] >> 32));
                float h  = lo + hi;                  // full dot product h_j
                rs += (h >= 0.f) ? h : 0.2f * h;     // leaky_relu
            }
#pragma unroll
            for (int off = 16; off > 0; off >>= 1)
                rs += __shfl_xor_sync(0xffffffffu, rs, off);
            if (lane == 0)
                s_sh[rel * 128 + r0 + r] = rs * 0.08838834764831845f; // 1/sqrt(128)
        }
        __syncthreads();   // protect I_sh/z_sh reuse and publish s_sh
    }

    // ---- phase C: softmax over relations + weighted combine -----------------
    const float4* n0g = reinterpret_cast<const float4*>(nb0);
    const float4* n1g = reinterpret_cast<const float4*>(nb1);
    const float4* n2g = reinterpret_cast<const float4*>(nb2);
    float4* og = reinterpret_cast<float4*>(out);

    for (int idx = tid; idx < 128 * 32; idx += 512) {
        int r  = idx >> 5;
        int c4 = idx & 31;
        if (r >= rows) continue;
        float s0 = s_sh[r];
        float s1 = s_sh[128 + r];
        float s2 = s_sh[256 + r];
        float m  = fmaxf(s0, fmaxf(s1, s2));
        float e0 = __expf(s0 - m);
        float e1 = __expf(s1 - m);
        float e2 = __expf(s2 - m);
        float inv = 1.f / (e0 + e1 + e2);
        float w0 = e0 * inv, w1 = e1 * inv, w2 = e2 * inv;

        size_t off = (size_t)(row0 + r) * 32 + c4;
        float4 av = n0g[off], bv = n1g[off], cv = n2g[off];
        float4 o;
        o.x = w0 * av.x + w1 * bv.x + w2 * cv.x;
        o.y = w0 * av.y + w1 * bv.y + w2 * cv.y;
        o.z = w0 * av.z + w1 * bv.z + w2 * cv.z;
        o.w = w0 * av.w + w1 * bv.w + w2 * cv.w;
        og[off] = o;
    }
}

// ---------------------------------------------------------------------------
// Launch
// ---------------------------------------------------------------------------
extern "C" void kernel_launch(void* const* d_in, const int* in_sizes, int n_in,
                              void* d_out, int out_size)
{
    // The scalar "b" may or may not occupy slot 0; detect by size.
    int base = (in_sizes[0] == 1) ? 1 : 0;

    const float* x      = (const float*)d_in[base + 0];
    const int*   src0   = (const int*  )d_in[base + 1];
    const int*   dst0   = (const int*  )d_in[base + 2];
    const float* val0   = (const float*)d_in[base + 3];
    const int*   src1   = (const int*  )d_in[base + 4];
    const int*   dst1   = (const int*  )d_in[base + 5];
    const float* val1   = (const float*)d_in[base + 6];
    const int*   src2   = (const int*  )d_in[base + 7];
    const int*   dst2   = (const int*  )d_in[base + 8];
    const float* val2   = (const float*)d_in[base + 9];
    const int*   src_ui = (const int*  )d_in[base + 10];
    const int*   dst_ui = (const int*  )d_in[base + 11];
    const float* val_ui = (const float*)d_in[base + 12];
    const float* I0     = (const float*)d_in[base + 13];
    const float* I1     = (const float*)d_in[base + 14];
    const float* I2     = (const float*)d_in[base + 15];

    int n_items = in_sizes[base + 0] / D_C;
    int E0  = in_sizes[base + 1];
    int E1  = in_sizes[base + 4];
    int E2  = in_sizes[base + 7];
    int Eui = in_sizes[base + 10];
    int n_users = out_size / D_C - n_items;

    float* out_f    = (float*)d_out;
    float* u_emb    = out_f;                          // tuple order: (u_emb, neighbor)
    float* neighbor = out_f + (size_t)n_users * D_C;

    float* nb_base = nullptr;
    cudaGetSymbolAddress((void**)&nb_base, g_nb);
    float* nb0 = nb_base;
    float* nb1 = nb_base + (size_t)n_items * D_C;
    float* nb2 = nb_base + (size_t)2 * n_items * D_C;

    // Zero the accumulation targets (d_out is poisoned; g_nb carries old data).
    cudaMemsetAsync(nb_base, 0, (size_t)3 * n_items * D_C * sizeof(float), 0);
    cudaMemsetAsync(u_emb,   0, (size_t)n_users * D_C * sizeof(float), 0);

    // SpMMs: 32 edges per 256-thread block (4 edges per warp).
    dim3 blk(256);
    spmm_kernel<<<(E0  + 31) / 32, blk>>>(src0,   dst0,   val0,   x, nb0,   E0 );
    spmm_kernel<<<(E1  + 31) / 32, blk>>>(src1,   dst1,   val1,   x, nb1,   E1 );
    spmm_kernel<<<(E2  + 31) / 32, blk>>>(src2,   dst2,   val2,   x, nb2,   E2 );
    spmm_kernel<<<(Eui + 31) / 32, blk>>>(src_ui, dst_ui, val_ui, x, u_emb, Eui);

    // Score + combine.
    const int smem_bytes = (64 * PITCHI + D_C * PITCH + 3 * 128) * (int)sizeof(float);
    cudaFuncSetAttribute(score_kernel,
                         cudaFuncAttributeMaxDynamicSharedMemorySize, smem_bytes);
    int nblocks = (n_items + 127) / 128;
    score_kernel<<<nblocks, 512, smem_bytes>>>(x, nb0, nb1, nb2, I0, I1, I2,
                                               neighbor, n_items);
}

// round 7
// speedup vs baseline: 1.3753x; 1.1989x over previous
#include <cuda_runtime.h>
#include <math.h>

// ---------------------------------------------------------------------------
// Problem constants (fixed by the dataset; runtime sizes still read from in_sizes)
// ---------------------------------------------------------------------------
#define D_C       128
#define PITCH     132          // z_sh row pitch (floats)
#define PITCHI    264          // paired-I row pitch (floats)
#define MAX_ITEMS 200000
#define MAX_USERS 100000
#define MAX_EII   3200000
#define MAX_EUI   1600000
#define MAX_EDGES (3 * MAX_EII + MAX_EUI)          // 11.2M
#define MAX_ROWS  (3 * MAX_ITEMS + MAX_USERS)      // 700K logical output rows

// Static device scratch (no allocs allowed).
__device__ float g_nb  [(size_t)3 * MAX_ITEMS * D_C];   // 3 item->item aggregates
__device__ int   g_bsrc[MAX_EDGES];                     // binned src indices
__device__ float g_bval[MAX_EDGES];                     // binned edge values
__device__ int   g_cnt [MAX_ROWS];                      // per-row edge counts
__device__ int   g_off [MAX_ROWS + 1];                  // CSR row offsets
__device__ int   g_cur [MAX_ROWS];                      // scatter cursors

// ---------------------------------------------------------------------------
// Pass 1: histogram of destination rows (4 edges / thread, int4 loads)
// ---------------------------------------------------------------------------
__global__ void hist_kernel(const int* __restrict__ dst, int nE, int base,
                            int* __restrict__ cnt)
{
    int i0 = (blockIdx.x * blockDim.x + threadIdx.x) * 4;
    if (i0 + 3 < nE) {
        int4 d = *reinterpret_cast<const int4*>(dst + i0);
        atomicAdd(&cnt[base + d.x], 1);
        atomicAdd(&cnt[base + d.y], 1);
        atomicAdd(&cnt[base + d.z], 1);
        atomicAdd(&cnt[base + d.w], 1);
    } else {
        for (int j = i0; j < nE; j++) atomicAdd(&cnt[base + dst[j]], 1);
    }
}

// ---------------------------------------------------------------------------
// Pass 2: single-block exclusive scan (4096 elements / iteration, shfl-based)
// Writes off[] and a working copy cur[]; off[N] = total.
// ---------------------------------------------------------------------------
__global__ void __launch_bounds__(1024)
scan_kernel(const int* __restrict__ cnt, int* __restrict__ off,
            int* __restrict__ cur, int N)
{
    __shared__ int wtot[32];
    __shared__ int wexcl[32];
    __shared__ int s_carry;
    const int tid = threadIdx.x, lane = tid & 31, wid = tid >> 5;
    if (tid == 0) s_carry = 0;
    __syncthreads();

    for (int base = 0; base < N; base += 4096) {
        int idx = base + tid * 4;
        int4 v = make_int4(0, 0, 0, 0);
        if (idx + 3 < N)      v = *reinterpret_cast<const int4*>(cnt + idx);
        else if (idx < N) {
            v.x = cnt[idx];
            if (idx + 1 < N) v.y = cnt[idx + 1];
            if (idx + 2 < N) v.z = cnt[idx + 2];
        }
        int t0 = v.x, t1 = t0 + v.y, t2 = t1 + v.z, t3 = t2 + v.w;

        int incl = t3;
#pragma unroll
        for (int o = 1; o < 32; o <<= 1) {
            int u = __shfl_up_sync(0xffffffffu, incl, o);
            if (lane >= o) incl += u;
        }
        int thr_excl = incl - t3;
        if (lane == 31) wtot[wid] = incl;
        __syncthreads();
        if (wid == 0) {
            int w = wtot[lane];
            int wi = w;
#pragma unroll
            for (int o = 1; o < 32; o <<= 1) {
                int u = __shfl_up_sync(0xffffffffu, wi, o);
                if (lane >= o) wi += u;
            }
            wexcl[lane] = wi - w;
            if (lane == 31) wtot[0] = wi;      // block total
        }
        __syncthreads();
        int carry = s_carry;
        int ex = carry + wexcl[wid] + thr_excl;
        if (idx + 3 < N) {
            int4 o4 = make_int4(ex, ex + t0, ex + t1, ex + t2);
            *reinterpret_cast<int4*>(off + idx) = o4;
            *reinterpret_cast<int4*>(cur + idx) = o4;
        } else if (idx < N) {
            off[idx] = ex;           cur[idx] = ex;
            if (idx + 1 < N) { off[idx + 1] = ex + t0; cur[idx + 1] = ex + t0; }
            if (idx + 2 < N) { off[idx + 2] = ex + t1; cur[idx + 2] = ex + t1; }
        }
        __syncthreads();
        if (tid == 0) s_carry = carry + wtot[0];
        __syncthreads();
    }
    if (tid == 0) off[N] = s_carry;
}

// ---------------------------------------------------------------------------
// Pass 3: scatter edges into their destination bins
// ---------------------------------------------------------------------------
__global__ void scatter_kernel(const int* __restrict__ src,
                               const int* __restrict__ dst,
                               const float* __restrict__ val,
                               int nE, int base, int* __restrict__ cur,
                               int* __restrict__ bsrc, float* __restrict__ bval)
{
    int i = blockIdx.x * blockDim.x + threadIdx.x;
    if (i < nE) {
        int d   = dst[i];
        int pos = atomicAdd(&cur[base + d], 1);
        bsrc[pos] = src[i];
        bval[pos] = val[i];
    }
}

// ---------------------------------------------------------------------------
// Pass 4: gather-accumulate. One warp per output row: register accumulation,
// single 512B store per row (no atomics, no memset needed).
// x gathers use an evict_last L2 policy (x is re-read ~56x per row).
// ---------------------------------------------------------------------------
__global__ void __launch_bounds__(256)
gather_kernel(const int* __restrict__ off,
              const int* __restrict__ bsrc,
              const float* __restrict__ bval,
              const float* __restrict__ x,
              float* __restrict__ nb, float* __restrict__ uemb,
              int n3, int nrows)
{
    int w = (blockIdx.x * blockDim.x + threadIdx.x) >> 5;
    if (w >= nrows) return;
    const int lane = threadIdx.x & 31;

    unsigned long long pol;
    asm("createpolicy.fractional.L2::evict_last.b64 %0, 1.0;" : "=l"(pol));

    int beg = __ldg(off + w);
    int end = __ldg(off + w + 1);

    float4 acc0 = make_float4(0.f, 0.f, 0.f, 0.f);
    float4 acc1 = make_float4(0.f, 0.f, 0.f, 0.f);

    for (int p = beg; p < end; p += 32) {
        int n = min(32, end - p);
        int s = 0; float v = 0.f;
        if (lane < n) { s = __ldg(bsrc + p + lane); v = __ldg(bval + p + lane); }
        for (int e = 0; e < n; e++) {
            int   se = __shfl_sync(0xffffffffu, s, e);
            float ve = __shfl_sync(0xffffffffu, v, e);
            const float* xp = x + (size_t)se * D_C + lane * 4;
            float4 t;
            asm volatile("ld.global.nc.L2::cache_hint.v4.f32 {%0,%1,%2,%3}, [%4], %5;"
                         : "=f"(t.x), "=f"(t.y), "=f"(t.z), "=f"(t.w)
                         : "l"(xp), "l"(pol));
            if (e & 1) {
                acc1.x = fmaf(t.x, ve, acc1.x); acc1.y = fmaf(t.y, ve, acc1.y);
                acc1.z = fmaf(t.z, ve, acc1.z); acc1.w = fmaf(t.w, ve, acc1.w);
            } else {
                acc0.x = fmaf(t.x, ve, acc0.x); acc0.y = fmaf(t.y, ve, acc0.y);
                acc0.z = fmaf(t.z, ve, acc0.z); acc0.w = fmaf(t.w, ve, acc0.w);
            }
        }
    }
    acc0.x += acc1.x; acc0.y += acc1.y; acc0.z += acc1.z; acc0.w += acc1.w;

    float* o = (w < n3) ? (nb + (size_t)w * D_C)
                        : (uemb + (size_t)(w - n3) * D_C);
    *reinterpret_cast<float4*>(o + lane * 4) = acc0;
}

// ---------------------------------------------------------------------------
// Score + combine kernel: 64 rows / block, 512 threads, 2 blocks/SM so the
// global staging of one block overlaps the FFMA2 loop of the other.
// ---------------------------------------------------------------------------
__device__ __forceinline__ unsigned long long ld_u64_smem(const float* p)
{
    return *reinterpret_cast<const unsigned long long*>(p);
}

__global__ void __launch_bounds__(512, 2)
score_kernel(const float* __restrict__ x,
             const float* __restrict__ nb0,
             const float* __restrict__ nb1,
             const float* __restrict__ nb2,
             const float* __restrict__ I0,
             const float* __restrict__ I1,
             const float* __restrict__ I2,
             float* __restrict__ out,
             int nrows)
{
    extern __shared__ float sm[];
    float* I_sh = sm;                              // 64 * PITCHI (paired k rows)
    float* z_sh = sm + 64 * PITCHI;                // 64 * PITCH
    float* s_sh = sm + 64 * PITCHI + 64 * PITCH;   // 3 * 64

    const int tid  = threadIdx.x;
    const int lane = tid & 31;
    const int wid  = tid >> 5;                     // 16 warps
    const int r0   = wid << 2;                     // 4 rows per warp
    const int row0 = blockIdx.x * 64;
    const int rows = min(64, nrows - row0);

    const float4* xg = reinterpret_cast<const float4*>(x);

#pragma unroll 1
    for (int rel = 0; rel < 3; rel++) {
        const float* nbp = (rel == 0) ? nb0 : (rel == 1) ? nb1 : nb2;
        const float* Ip  = (rel == 0) ? I0  : (rel == 1) ? I1  : I2;

        // ---- stage I as k-pair-interleaved rows (full 128x128) -------------
        const float4* Ig = reinterpret_cast<const float4*>(Ip);
        for (int idx = tid; idx < 64 * 32; idx += 512) {
            int p  = idx >> 5;
            int j4 = idx & 31;
            float4 ae = Ig[(2 * p)     * 32 + j4];
            float4 ao = Ig[(2 * p + 1) * 32 + j4];
            float* w = &I_sh[p * PITCHI + (j4 << 3)];
            *reinterpret_cast<float4*>(w)     = make_float4(ae.x, ao.x, ae.y, ao.y);
            *reinterpret_cast<float4*>(w + 4) = make_float4(ae.z, ao.z, ae.w, ao.w);
        }
        // ---- stage z = x * nb (64 rows) -------------------------------------
        const float4* ng = reinterpret_cast<const float4*>(nbp);
        for (int idx = tid; idx < 64 * 32; idx += 512) {
            int r  = idx >> 5;
            int k4 = idx & 31;
            float4 zv = make_float4(0.f, 0.f, 0.f, 0.f);
            if (r < rows) {
                size_t offr = (size_t)(row0 + r) * 32 + k4;
                float4 av = xg[offr];
                float4 bv = ng[offr];
                zv.x = av.x * bv.x; zv.y = av.y * bv.y;
                zv.z = av.z * bv.z; zv.w = av.w * bv.w;
            }
            *reinterpret_cast<float4*>(&z_sh[r * PITCH + (k4 << 2)]) = zv;
        }
        __syncthreads();

        // ---- register-tiled matvec with FFMA2 -------------------------------
        unsigned long long acc[4][4];
#pragma unroll
        for (int r = 0; r < 4; r++)
#pragma unroll
            for (int c = 0; c < 4; c++) acc[r][c] = 0ull;

        for (int p = 0; p < 64; p++) {
            unsigned long long zp[4];
#pragma unroll
            for (int r = 0; r < 4; r++)
                zp[r] = ld_u64_smem(&z_sh[(r0 + r) * PITCH + 2 * p]);
#pragma unroll
            for (int c = 0; c < 4; c++) {
                unsigned long long bp =
                    ld_u64_smem(&I_sh[p * PITCHI + ((lane + 32 * c) << 1)]);
#pragma unroll
                for (int r = 0; r < 4; r++)
                    asm("fma.rn.f32x2 %0, %1, %2, %0;"
                        : "+l"(acc[r][c]) : "l"(zp[r]), "l"(bp));
            }
        }

        // ---- leaky_relu + column sum + warp reduce --------------------------
#pragma unroll
        for (int r = 0; r < 4; r++) {
            float rs = 0.f;
#pragma unroll
            for (int c = 0; c < 4; c++) {
                float lo = __int_as_float((int)(acc[r][c] & 0xffffffffull));
                float hi = __int_as_float((int)(acc[r][c] >> 32));
                float h  = lo + hi;
                rs += (h >= 0.f) ? h : 0.2f * h;
            }
#pragma unroll
            for (int o = 16; o > 0; o >>= 1)
                rs += __shfl_xor_sync(0xffffffffu, rs, o);
            if (lane == 0)
                s_sh[rel * 64 + r0 + r] = rs * 0.08838834764831845f; // 1/sqrt(128)
        }
        __syncthreads();
    }

    // ---- softmax over relations + weighted combine ---------------------------
    const float4* n0g = reinterpret_cast<const float4*>(nb0);
    const float4* n1g = reinterpret_cast<const float4*>(nb1);
    const float4* n2g = reinterpret_cast<const float4*>(nb2);
    float4* og = reinterpret_cast<float4*>(out);

    for (int idx = tid; idx < 64 * 32; idx += 512) {
        int r  = idx >> 5;
        int c4 = idx & 31;
        if (r >= rows) continue;
        float s0 = s_sh[r];
        float s1 = s_sh[64 + r];
        float s2 = s_sh[128 + r];
        float m  = fmaxf(s0, fmaxf(s1, s2));
        float e0 = __expf(s0 - m);
        float e1 = __expf(s1 - m);
        float e2 = __expf(s2 - m);
        float inv = 1.f / (e0 + e1 + e2);
        float w0 = e0 * inv, w1 = e1 * inv, w2 = e2 * inv;

        size_t offr = (size_t)(row0 + r) * 32 + c4;
        float4 av = n0g[offr], bv = n1g[offr], cv = n2g[offr];
        float4 o;
        o.x = w0 * av.x + w1 * bv.x + w2 * cv.x;
        o.y = w0 * av.y + w1 * bv.y + w2 * cv.y;
        o.z = w0 * av.z + w1 * bv.z + w2 * cv.z;
        o.w = w0 * av.w + w1 * bv.w + w2 * cv.w;
        og[offr] = o;
    }
}

// ---------------------------------------------------------------------------
// Launch
// ---------------------------------------------------------------------------
extern "C" void kernel_launch(void* const* d_in, const int* in_sizes, int n_in,
                              void* d_out, int out_size)
{
    int base = (in_sizes[0] == 1) ? 1 : 0;

    const float* x      = (const float*)d_in[base + 0];
    const int*   srcs[4] = { (const int*)d_in[base + 1], (const int*)d_in[base + 4],
                             (const int*)d_in[base + 7], (const int*)d_in[base + 10] };
    const int*   dsts[4] = { (const int*)d_in[base + 2], (const int*)d_in[base + 5],
                             (const int*)d_in[base + 8], (const int*)d_in[base + 11] };
    const float* vals[4] = { (const float*)d_in[base + 3], (const float*)d_in[base + 6],
                             (const float*)d_in[base + 9], (const float*)d_in[base + 12] };
    const float* I0     = (const float*)d_in[base + 13];
    const float* I1     = (const float*)d_in[base + 14];
    const float* I2     = (const float*)d_in[base + 15];

    int n_items = in_sizes[base + 0] / D_C;
    int nE[4]   = { in_sizes[base + 1], in_sizes[base + 4],
                    in_sizes[base + 7], in_sizes[base + 10] };
    int n_users = out_size / D_C - n_items;
    int n3      = 3 * n_items;
    int nrows   = n3 + n_users;

    float* out_f    = (float*)d_out;
    float* u_emb    = out_f;                          // tuple order: (u_emb, neighbor)
    float* neighbor = out_f + (size_t)n_users * D_C;

    float *nb_base, *bval; int *bsrc, *cnt, *off, *cur;
    cudaGetSymbolAddress((void**)&nb_base, g_nb);
    cudaGetSymbolAddress((void**)&bsrc,    g_bsrc);
    cudaGetSymbolAddress((void**)&bval,    g_bval);
    cudaGetSymbolAddress((void**)&cnt,     g_cnt);
    cudaGetSymbolAddress((void**)&off,     g_off);
    cudaGetSymbolAddress((void**)&cur,     g_cur);

    float* nb0 = nb_base;
    float* nb1 = nb_base + (size_t)n_items * D_C;
    float* nb2 = nb_base + (size_t)2 * n_items * D_C;

    // --- build CSR bins -----------------------------------------------------
    cudaMemsetAsync(cnt, 0, (size_t)nrows * sizeof(int), 0);
    for (int r = 0; r < 4; r++) {
        int b = (r < 3) ? r * n_items : n3;
        int g = ((nE[r] + 3) / 4 + 255) / 256;
        hist_kernel<<<g, 256>>>(dsts[r], nE[r], b, cnt);
    }
    scan_kernel<<<1, 1024>>>(cnt, off, cur, nrows);
    for (int r = 0; r < 4; r++) {
        int b = (r < 3) ? r * n_items : n3;
        int g = (nE[r] + 255) / 256;
        scatter_kernel<<<g, 256>>>(srcs[r], dsts[r], vals[r], nE[r], b, cur,
                                   bsrc, bval);
    }

    // --- gather-accumulate: writes nb0..2 and u_emb (no memset needed) -------
    {
        int g = ((nrows * 32) + 255) / 256;
        gather_kernel<<<g, 256>>>(off, bsrc, bval, x, nb_base, u_emb, n3, nrows);
    }

    // --- score + combine ------------------------------------------------------
    const int smem_bytes = (64 * PITCHI + 64 * PITCH + 3 * 64) * (int)sizeof(float);
    cudaFuncSetAttribute(score_kernel,
                         cudaFuncAttributeMaxDynamicSharedMemorySize, smem_bytes);
    int nblocks = (n_items + 63) / 64;
    score_kernel<<<nblocks, 512, smem_bytes>>>(x, nb0, nb1, nb2, I0, I1, I2,
                                               neighbor, n_items);
}